// round 1
// baseline (speedup 1.0000x reference)
#include <cuda_runtime.h>
#include <math.h>

#define D_MODEL 256
#define D_FFN   1024
#define NHEADS  8
#define NLEV    4
#define NPTS    4
#define HDIM    32
#define BATCH   2
#define SLEN    21760
#define NTOK    (BATCH * SLEN)   // 43520

// ---------------- scratch (device globals; no allocation allowed) ----------------
__device__ float g_q[NTOK * D_MODEL];
__device__ float g_value[NTOK * D_MODEL];
__device__ float g_off[NTOK * D_MODEL];            // [tok, h, lvl, p, 2] = 256
__device__ float g_attn[NTOK * NHEADS * 16];       // [tok, h, lvl*4+p]
__device__ float g_samp[NTOK * D_MODEL];           // deform attn output [tok, h*32+d]
__device__ float g_src2[NTOK * D_MODEL];           // src + attn_out
__device__ float g_h2[NTOK * D_MODEL];             // ln2 output
__device__ float g_ffn[NTOK * D_FFN];              // gelu(ffn1)

// ---------------- layernorm (+ optional additive term) ----------------
// one block (256 threads) per token
__global__ void ln_kernel(const float* __restrict__ x,
                          const float* __restrict__ gamma,
                          const float* __restrict__ beta,
                          const float* __restrict__ add,   // may be null
                          float* __restrict__ out) {
    int t = blockIdx.x;
    int c = threadIdx.x;
    float v = x[t * D_MODEL + c];
    float a = v, a2 = v * v;
    #pragma unroll
    for (int o = 16; o; o >>= 1) {
        a  += __shfl_xor_sync(0xffffffffu, a,  o);
        a2 += __shfl_xor_sync(0xffffffffu, a2, o);
    }
    __shared__ float s1[8], s2[8];
    if ((c & 31) == 0) { s1[c >> 5] = a; s2[c >> 5] = a2; }
    __syncthreads();
    float sum = 0.f, sq = 0.f;
    #pragma unroll
    for (int i = 0; i < 8; i++) { sum += s1[i]; sq += s2[i]; }
    float mu  = sum * (1.0f / D_MODEL);
    float var = sq * (1.0f / D_MODEL) - mu * mu;
    float r   = rsqrtf(var + 1e-5f);
    float y   = (v - mu) * r * gamma[c] + beta[c];
    if (add) y += add[t * D_MODEL + c];
    out[t * D_MODEL + c] = y;
}

// ---------------- generic fp32 GEMM: C = epi(A@W + bias [, +R]) ----------------
// EPI: 0 = bias only, 1 = gelu(x+bias), 2 = x+bias+R (residual)
// Tiles: BM=BN=64, BK=16; 256 threads, 4x4 microtile. M,N,K multiples of tiles.
__device__ __forceinline__ float gelu_exact(float x) {
    return 0.5f * x * (1.0f + erff(x * 0.70710678118654752f));
}

template <int EPI>
__global__ void gemm_kernel(const float* __restrict__ A, const float* __restrict__ W,
                            const float* __restrict__ bias, const float* __restrict__ R,
                            float* __restrict__ C, int M, int N, int K) {
    __shared__ float As[16][68];   // [k][m], padded
    __shared__ float Bs[16][64];   // [k][n]

    int tid = threadIdx.x;
    int tx = tid & 15, ty = tid >> 4;
    int m0 = blockIdx.y * 64, n0 = blockIdx.x * 64;

    float acc[4][4] = {};

    for (int k0 = 0; k0 < K; k0 += 16) {
        #pragma unroll
        for (int i = 0; i < 4; i++) {
            int idx = tid + i * 256;
            int r = idx >> 4, c = idx & 15;               // A: 64 rows x 16 k
            As[c][r] = A[(size_t)(m0 + r) * K + k0 + c];
            int rb = idx >> 6, cb = idx & 63;             // B: 16 k x 64 cols
            Bs[rb][cb] = W[(size_t)(k0 + rb) * N + n0 + cb];
        }
        __syncthreads();
        #pragma unroll
        for (int k = 0; k < 16; k++) {
            float4 av = *(const float4*)&As[k][ty * 4];
            float4 bv = *(const float4*)&Bs[k][tx * 4];
            float am[4] = {av.x, av.y, av.z, av.w};
            float bm[4] = {bv.x, bv.y, bv.z, bv.w};
            #pragma unroll
            for (int i = 0; i < 4; i++)
                #pragma unroll
                for (int j = 0; j < 4; j++)
                    acc[i][j] = fmaf(am[i], bm[j], acc[i][j]);
        }
        __syncthreads();
    }

    #pragma unroll
    for (int i = 0; i < 4; i++) {
        int row = m0 + ty * 4 + i;
        #pragma unroll
        for (int j = 0; j < 4; j++) {
            int col = n0 + tx * 4 + j;
            float v = acc[i][j] + bias[col];
            if (EPI == 1) v = gelu_exact(v);
            if (EPI == 2) v += R[(size_t)row * N + col];
            C[(size_t)row * N + col] = v;
        }
    }
}

// ---------------- softmax over 16 (per token, per head) ----------------
__global__ void softmax16_kernel(float* __restrict__ a, int n) {
    int i = blockIdx.x * blockDim.x + threadIdx.x;
    if (i >= n) return;
    float* p = a + (size_t)i * 16;
    float m = -1e30f;
    float v[16];
    #pragma unroll
    for (int j = 0; j < 16; j++) { v[j] = p[j]; m = fmaxf(m, v[j]); }
    float s = 0.f;
    #pragma unroll
    for (int j = 0; j < 16; j++) { v[j] = __expf(v[j] - m); s += v[j]; }
    float inv = 1.0f / s;
    #pragma unroll
    for (int j = 0; j < 16; j++) p[j] = v[j] * inv;
}

// ---------------- deformable attention sampling ----------------
// one warp per (b, q, h); lane = head dim (32)
__global__ void deform_kernel(const float* __restrict__ ref /* [B,L,4,2] */,
                              float* __restrict__ out /* g_samp */) {
    const int lvH[4] = {128, 64, 32, 16};
    const int lvW[4] = {128, 64, 32, 16};
    const int lvS[4] = {0, 16384, 20480, 21504};

    int g = blockIdx.x * 8 + (threadIdx.x >> 5);
    int lane = threadIdx.x & 31;
    int b  = g / (SLEN * NHEADS);
    int rm = g - b * (SLEN * NHEADS);
    int qi = rm / NHEADS;
    int h  = rm - qi * NHEADS;
    int tok = b * SLEN + qi;

    float acc = 0.f;
    #pragma unroll
    for (int lvl = 0; lvl < NLEV; lvl++) {
        const int Hh = lvH[lvl], Ww = lvW[lvl], st = lvS[lvl];
        float rx = ref[((size_t)tok * NLEV + lvl) * 2 + 0];
        float ry = ref[((size_t)tok * NLEV + lvl) * 2 + 1];
        #pragma unroll
        for (int p = 0; p < NPTS; p++) {
            const float* op = g_off + (size_t)tok * 256 + (((h * NLEV + lvl) * NPTS + p) * 2);
            float x = rx * (float)Ww + op[0] - 0.5f;
            float y = ry * (float)Hh + op[1] - 0.5f;
            float w = g_attn[(size_t)tok * 128 + h * 16 + lvl * 4 + p];

            float x0f = floorf(x), y0f = floorf(y);
            int x0 = (int)x0f, y0 = (int)y0f;
            float wx = x - x0f, wy = y - y0f;

            float v00 = 0.f, v01 = 0.f, v10 = 0.f, v11 = 0.f;
            int x1 = x0 + 1, y1 = y0 + 1;
            bool vx0 = (x0 >= 0) & (x0 < Ww);
            bool vx1 = (x1 >= 0) & (x1 < Ww);
            bool vy0 = (y0 >= 0) & (y0 < Hh);
            bool vy1 = (y1 >= 0) & (y1 < Hh);
            size_t rowBase = (size_t)(b * SLEN + st);
            if (vy0) {
                size_t rb = (rowBase + (size_t)y0 * Ww) * NHEADS;
                if (vx0) v00 = g_value[((rb + (size_t)x0 * NHEADS) + h) * HDIM + lane];
                if (vx1) v01 = g_value[((rb + (size_t)x1 * NHEADS) + h) * HDIM + lane];
            }
            if (vy1) {
                size_t rb = (rowBase + (size_t)y1 * Ww) * NHEADS;
                if (vx0) v10 = g_value[((rb + (size_t)x0 * NHEADS) + h) * HDIM + lane];
                if (vx1) v11 = g_value[((rb + (size_t)x1 * NHEADS) + h) * HDIM + lane];
            }
            float top = v00 + (v01 - v00) * wx;
            float bot = v10 + (v11 - v10) * wx;
            acc += w * (top + (bot - top) * wy);
        }
    }
    out[((size_t)tok * NHEADS + h) * HDIM + lane] = acc;
}

// NOTE: g_value is indexed [b*L + pos][h][d]; rb above pre-multiplies by NHEADS,
// and x*NHEADS is wrong unless we multiply by NHEADS per spatial step — fix:
// rewrite index cleanly in a helper to avoid mistakes (done below via macro form).

// ---------------- launch ----------------
extern "C" void kernel_launch(void* const* d_in, const int* in_sizes, int n_in,
                              void* d_out, int out_size) {
    const float* src   = (const float*)d_in[0];
    const float* pos   = (const float*)d_in[1];
    const float* refp  = (const float*)d_in[2];
    // d_in[3] spatial_shapes (int), d_in[4] level_start_index (int): compile-time constants
    const float* n1g = (const float*)d_in[5];
    const float* n1b = (const float*)d_in[6];
    const float* n2g = (const float*)d_in[7];
    const float* n2b = (const float*)d_in[8];
    const float* Wv  = (const float*)d_in[9];
    const float* bv  = (const float*)d_in[10];
    const float* Wo  = (const float*)d_in[11];
    const float* bo  = (const float*)d_in[12];
    const float* Wa  = (const float*)d_in[13];
    const float* ba  = (const float*)d_in[14];
    const float* Wout= (const float*)d_in[15];
    const float* bout= (const float*)d_in[16];
    const float* Wf1 = (const float*)d_in[17];
    const float* bf1 = (const float*)d_in[18];
    const float* Wf2 = (const float*)d_in[19];
    const float* bf2 = (const float*)d_in[20];
    float* out = (float*)d_out;

    float *p_q, *p_val, *p_off, *p_attn, *p_samp, *p_src2, *p_h2, *p_ffn;
    cudaGetSymbolAddress((void**)&p_q,    g_q);
    cudaGetSymbolAddress((void**)&p_val,  g_value);
    cudaGetSymbolAddress((void**)&p_off,  g_off);
    cudaGetSymbolAddress((void**)&p_attn, g_attn);
    cudaGetSymbolAddress((void**)&p_samp, g_samp);
    cudaGetSymbolAddress((void**)&p_src2, g_src2);
    cudaGetSymbolAddress((void**)&p_h2,   g_h2);
    cudaGetSymbolAddress((void**)&p_ffn,  g_ffn);

    dim3 t256(256);

    // 1. q = LN1(src) + pos
    ln_kernel<<<NTOK, t256>>>(src, n1g, n1b, pos, p_q);

    // 2. value = src @ Wv + bv
    gemm_kernel<0><<<dim3(D_MODEL / 64, NTOK / 64), t256>>>(src, Wv, bv, nullptr, p_val, NTOK, D_MODEL, D_MODEL);

    // 3. offsets = q @ Woff + boff
    gemm_kernel<0><<<dim3(D_MODEL / 64, NTOK / 64), t256>>>(p_q, Wo, bo, nullptr, p_off, NTOK, D_MODEL, D_MODEL);

    // 4. attn logits = q @ Wattn + battn  (N=128)
    gemm_kernel<0><<<dim3(128 / 64, NTOK / 64), t256>>>(p_q, Wa, ba, nullptr, p_attn, NTOK, 128, D_MODEL);

    // 5. softmax over 16 per (token, head)
    {
        int n = NTOK * NHEADS;
        softmax16_kernel<<<(n + 255) / 256, t256>>>(p_attn, n);
    }

    // 6. deformable sampling
    deform_kernel<<<(NTOK * NHEADS) / 8, t256>>>(refp, p_samp);

    // 7. src2 = src + samp @ Wout + bout
    gemm_kernel<2><<<dim3(D_MODEL / 64, NTOK / 64), t256>>>(p_samp, Wout, bout, src, p_src2, NTOK, D_MODEL, D_MODEL);

    // 8. h2 = LN2(src2)
    ln_kernel<<<NTOK, t256>>>(p_src2, n2g, n2b, nullptr, p_h2);

    // 9. ffn = gelu(h2 @ Wf1 + bf1)
    gemm_kernel<1><<<dim3(D_FFN / 64, NTOK / 64), t256>>>(p_h2, Wf1, bf1, nullptr, p_ffn, NTOK, D_FFN, D_MODEL);

    // 10. out = src2 + ffn @ Wf2 + bf2
    gemm_kernel<2><<<dim3(D_MODEL / 64, NTOK / 64), t256>>>(p_ffn, Wf2, bf2, p_src2, out, NTOK, D_MODEL, D_FFN);
}

// round 3
// speedup vs baseline: 1.9527x; 1.9527x over previous
#include <cuda_runtime.h>
#include <cuda_bf16.h>
#include <math.h>
#include <stdint.h>

#define D_MODEL 256
#define D_FFN   1024
#define NHEADS  8
#define NLEV    4
#define NPTS    4
#define HDIM    32
#define BATCH   2
#define SLEN    21760
#define NTOK    (BATCH * SLEN)   // 43520

// ================= scratch (device globals; no allocation allowed) =================
// activations in bf16x3 "cat-K" layout: [hi(0..K-1) | hi | lo], row length 3K
__device__ __align__(16) __nv_bfloat16 g_src3[NTOK * 768];
__device__ __align__(16) __nv_bfloat16 g_q3[NTOK * 768];
__device__ __align__(16) __nv_bfloat16 g_samp3[NTOK * 768];
__device__ __align__(16) __nv_bfloat16 g_h23[NTOK * 768];
__device__ __align__(16) __nv_bfloat16 g_ffn3[NTOK * 3072];

__device__ float g_value[NTOK * D_MODEL];
__device__ float g_off[NTOK * D_MODEL];
__device__ float g_attn[NTOK * NHEADS * 16];
__device__ float g_src2[NTOK * D_MODEL];

// weights in bf16x3 cat-K layout, transposed: B3[N][3K] = [hi | lo | hi]
__device__ __align__(16) __nv_bfloat16 w3_v[256 * 768];
__device__ __align__(16) __nv_bfloat16 w3_of[256 * 768];
__device__ __align__(16) __nv_bfloat16 w3_at[128 * 768];
__device__ __align__(16) __nv_bfloat16 w3_o[256 * 768];
__device__ __align__(16) __nv_bfloat16 w3_f1[1024 * 768];
__device__ __align__(16) __nv_bfloat16 w3_f2[256 * 3072];

// ================= helpers =================
__device__ __forceinline__ uint32_t smem_u32(const void* p) {
    uint32_t a;
    asm("{ .reg .u64 t; cvta.to.shared.u64 t, %1; cvt.u32.u64 %0, t; }" : "=r"(a) : "l"(p));
    return a;
}
__device__ __forceinline__ void ldm_x4(uint32_t* r, uint32_t addr) {
    asm volatile("ldmatrix.sync.aligned.m8n8.x4.shared.b16 {%0,%1,%2,%3}, [%4];"
                 : "=r"(r[0]), "=r"(r[1]), "=r"(r[2]), "=r"(r[3]) : "r"(addr));
}
__device__ __forceinline__ void mma16816(float* d, const uint32_t* a, const uint32_t* b) {
    asm volatile("mma.sync.aligned.m16n8k16.row.col.f32.bf16.bf16.f32 "
                 "{%0,%1,%2,%3}, {%4,%5,%6,%7}, {%8,%9}, {%0,%1,%2,%3};"
                 : "+f"(d[0]), "+f"(d[1]), "+f"(d[2]), "+f"(d[3])
                 : "r"(a[0]), "r"(a[1]), "r"(a[2]), "r"(a[3]), "r"(b[0]), "r"(b[1]));
}
__device__ __forceinline__ void cpa16(uint32_t dst, const void* src) {
    asm volatile("cp.async.cg.shared.global [%0], [%1], 16;" :: "r"(dst), "l"(src));
}
__device__ __forceinline__ void split2(float x, __nv_bfloat16& h, __nv_bfloat16& l) {
    h = __float2bfloat16(x);
    l = __float2bfloat16(x - __bfloat162float(h));
}

// ================= HMMA GEMM: C[M,N] = epi(A3[M,K3] @ (B3[N,K3])^T + bias) =================
// EPI: 0 = bias, fp32 out; 1 = gelu(x+bias) -> bf16x3 cat out (rowlen 3N); 2 = x+bias+R, fp32 out.
// Tile 128x128, BK=64, double-buffered cp.async, 8 warps of 64x32. K3 % 64 == 0.
static const int LDS  = 72;                  // bf16 elements per smem row (64 + 8 pad)
static const int LDSB = LDS * 2;             // 144 bytes
static const int BUFB = 128 * LDSB;          // 18432 bytes per operand tile
static const int GEMM_SMEM = 4 * BUFB;       // 73728: 2 stages x (A,B); also epilogue space

template <int EPI>
__global__ void __launch_bounds__(256, 2) mma_gemm(
    const __nv_bfloat16* __restrict__ A, const __nv_bfloat16* __restrict__ B,
    const float* __restrict__ bias, const float* __restrict__ R,
    float* __restrict__ C, __nv_bfloat16* __restrict__ C3,
    int N, int K)
{
    extern __shared__ __align__(16) char sm[];
    const uint32_t smb = smem_u32(sm);
    // buffers: [A0][B0][A1][B1]
    const int tid = threadIdx.x;
    const int wid = tid >> 5, lane = tid & 31;
    const int wm = wid >> 2, wn = wid & 3;               // 2 x 4 warps
    const int m0 = blockIdx.y * 128, n0 = blockIdx.x * 128;
    const int S = K >> 6;

    float acc[4][4][4];
    #pragma unroll
    for (int i = 0; i < 4; i++)
        #pragma unroll
        for (int j = 0; j < 4; j++)
            #pragma unroll
            for (int r = 0; r < 4; r++) acc[i][j][r] = 0.f;

    auto prefetch = [&](int s) {
        const int k0 = s << 6;
        const uint32_t ab = smb + (uint32_t)(s & 1) * (2u * BUFB);
        const uint32_t bb = ab + BUFB;
        #pragma unroll
        for (int i = 0; i < 8; i++) {
            int c = tid + (i << 8);                      // 0..2047
            int cc = c & 1023;
            int row = cc >> 3;
            int kc  = (cc & 7) << 3;                     // bf16 elem offset (16B chunks)
            uint32_t dst; const __nv_bfloat16* src;
            if (c < 1024) {
                dst = ab + (uint32_t)(row * LDSB + kc * 2);
                src = A + (size_t)(m0 + row) * K + k0 + kc;
            } else {
                dst = bb + (uint32_t)(row * LDSB + kc * 2);
                src = B + (size_t)(n0 + row) * K + k0 + kc;
            }
            cpa16(dst, src);
        }
        asm volatile("cp.async.commit_group;");
    };

    prefetch(0);

    for (int s = 0; s < S; s++) {
        if (s + 1 < S) {
            prefetch(s + 1);
            asm volatile("cp.async.wait_group 1;");
        } else {
            asm volatile("cp.async.wait_group 0;");
        }
        __syncthreads();

        const uint32_t ab = smb + (uint32_t)(s & 1) * (2u * BUFB);
        const uint32_t bb = ab + BUFB;
        const uint32_t aoff = ab + (uint32_t)(((lane & 15) + wm * 64) * LDSB + (((lane >> 4) << 3)) * 2);
        const uint32_t boff = bb + (uint32_t)((((lane & 7) + ((lane >> 4) << 3)) + wn * 32) * LDSB
                                              + ((((lane >> 3) & 1) << 3)) * 2);
        #pragma unroll
        for (int ks = 0; ks < 4; ks++) {
            const uint32_t kb = (uint32_t)(ks * 16 * 2);
            uint32_t afr[4][4], bfr[4][2];
            #pragma unroll
            for (int mi = 0; mi < 4; mi++)
                ldm_x4(afr[mi], aoff + (uint32_t)(mi * 16 * LDSB) + kb);
            #pragma unroll
            for (int nj = 0; nj < 2; nj++) {
                uint32_t r[4];
                ldm_x4(r, boff + (uint32_t)(nj * 16 * LDSB) + kb);
                bfr[nj * 2][0] = r[0]; bfr[nj * 2][1] = r[1];
                bfr[nj * 2 + 1][0] = r[2]; bfr[nj * 2 + 1][1] = r[3];
            }
            #pragma unroll
            for (int mi = 0; mi < 4; mi++)
                #pragma unroll
                for (int ni = 0; ni < 4; ni++)
                    mma16816(acc[mi][ni], afr[mi], bfr[ni]);
        }
        __syncthreads();
    }

    // ---- epilogue: stage each warp's 64x32 tile in smem (stride 36), store coalesced ----
    float* ws = (float*)sm + wid * (64 * 36);
    const int er = lane >> 2, ec = (lane & 3) * 2;
    #pragma unroll
    for (int mi = 0; mi < 4; mi++)
        #pragma unroll
        for (int ni = 0; ni < 4; ni++) {
            *(float2*)&ws[(mi * 16 + er) * 36 + ni * 8 + ec]     = make_float2(acc[mi][ni][0], acc[mi][ni][1]);
            *(float2*)&ws[(mi * 16 + er + 8) * 36 + ni * 8 + ec] = make_float2(acc[mi][ni][2], acc[mi][ni][3]);
        }
    __syncwarp();

    const int gc = n0 + wn * 32 + lane;
    const float bb = bias[gc];
    for (int r = 0; r < 64; r++) {
        float v = ws[r * 36 + lane] + bb;
        const int gr = m0 + wm * 64 + r;
        if (EPI == 1) {
            v = 0.5f * v * (1.0f + erff(v * 0.70710678118654752f));
            __nv_bfloat16 h, l; split2(v, h, l);
            size_t base = (size_t)gr * (3 * (size_t)N);
            C3[base + gc] = h;
            C3[base + N + gc] = h;
            C3[base + 2 * N + gc] = l;
        } else {
            if (EPI == 2) v += R[(size_t)gr * N + gc];
            C[(size_t)gr * N + gc] = v;
        }
    }
}

// ================= layernorm -> bf16x3 cat (+ optional additive term) =================
__global__ void ln_kernel(const float* __restrict__ x,
                          const float* __restrict__ gamma,
                          const float* __restrict__ beta,
                          const float* __restrict__ add,
                          __nv_bfloat16* __restrict__ o3) {
    int t = blockIdx.x;
    int c = threadIdx.x;
    float v = x[t * D_MODEL + c];
    float a = v, a2 = v * v;
    #pragma unroll
    for (int o = 16; o; o >>= 1) {
        a  += __shfl_xor_sync(0xffffffffu, a,  o);
        a2 += __shfl_xor_sync(0xffffffffu, a2, o);
    }
    __shared__ float s1[8], s2[8];
    if ((c & 31) == 0) { s1[c >> 5] = a; s2[c >> 5] = a2; }
    __syncthreads();
    float sum = 0.f, sq = 0.f;
    #pragma unroll
    for (int i = 0; i < 8; i++) { sum += s1[i]; sq += s2[i]; }
    float mu  = sum * (1.0f / D_MODEL);
    float var = sq * (1.0f / D_MODEL) - mu * mu;
    float rr  = rsqrtf(var + 1e-5f);
    float y   = (v - mu) * rr * gamma[c] + beta[c];
    if (add) y += add[t * D_MODEL + c];
    __nv_bfloat16 h, l; split2(y, h, l);
    size_t base = (size_t)t * 768;
    o3[base + c] = h;
    o3[base + 256 + c] = h;
    o3[base + 512 + c] = l;
}

// ================= fp32 [M,256] -> bf16x3 cat =================
__global__ void split_kernel(const float* __restrict__ x, __nv_bfloat16* __restrict__ o3) {
    int i = blockIdx.x * blockDim.x + threadIdx.x;
    if (i >= NTOK * D_MODEL) return;
    int t = i >> 8, c = i & 255;
    __nv_bfloat16 h, l; split2(x[i], h, l);
    size_t base = (size_t)t * 768;
    o3[base + c] = h;
    o3[base + 256 + c] = h;
    o3[base + 512 + c] = l;
}

// ================= weight prep: W[K,N] -> B3[N][3K] = [hi | lo | hi] =================
__global__ void wprep_kernel(const float* __restrict__ W, __nv_bfloat16* __restrict__ B3,
                             int K, int N) {
    int i = blockIdx.x * blockDim.x + threadIdx.x;
    if (i >= K * N) return;
    int k = i / N, n = i - k * N;
    __nv_bfloat16 h, l; split2(W[i], h, l);
    size_t base = (size_t)n * (3 * (size_t)K);
    B3[base + k] = h;
    B3[base + K + k] = l;
    B3[base + 2 * K + k] = h;
}

// ================= softmax over 16 =================
__global__ void softmax16_kernel(float* __restrict__ a, int n) {
    int i = blockIdx.x * blockDim.x + threadIdx.x;
    if (i >= n) return;
    float* p = a + (size_t)i * 16;
    float m = -1e30f;
    float v[16];
    #pragma unroll
    for (int j = 0; j < 16; j++) { v[j] = p[j]; m = fmaxf(m, v[j]); }
    float s = 0.f;
    #pragma unroll
    for (int j = 0; j < 16; j++) { v[j] = __expf(v[j] - m); s += v[j]; }
    float inv = 1.0f / s;
    #pragma unroll
    for (int j = 0; j < 16; j++) p[j] = v[j] * inv;
}

// ================= deformable attention sampling -> bf16x3 cat =================
__global__ void deform_kernel(const float* __restrict__ ref, __nv_bfloat16* __restrict__ o3) {
    const int lvH[4] = {128, 64, 32, 16};
    const int lvW[4] = {128, 64, 32, 16};
    const int lvS[4] = {0, 16384, 20480, 21504};

    int g = blockIdx.x * 8 + (threadIdx.x >> 5);
    int lane = threadIdx.x & 31;
    int b  = g / (SLEN * NHEADS);
    int rm = g - b * (SLEN * NHEADS);
    int qi = rm / NHEADS;
    int h  = rm - qi * NHEADS;
    int tok = b * SLEN + qi;

    float acc = 0.f;
    #pragma unroll
    for (int lvl = 0; lvl < NLEV; lvl++) {
        const int Hh = lvH[lvl], Ww = lvW[lvl], st = lvS[lvl];
        float rx = ref[((size_t)tok * NLEV + lvl) * 2 + 0];
        float ry = ref[((size_t)tok * NLEV + lvl) * 2 + 1];
        #pragma unroll
        for (int p = 0; p < NPTS; p++) {
            const float* op = g_off + (size_t)tok * 256 + (((h * NLEV + lvl) * NPTS + p) * 2);
            float x = rx * (float)Ww + op[0] - 0.5f;
            float y = ry * (float)Hh + op[1] - 0.5f;
            float w = g_attn[(size_t)tok * 128 + h * 16 + lvl * 4 + p];

            float x0f = floorf(x), y0f = floorf(y);
            int x0 = (int)x0f, y0 = (int)y0f;
            float wx = x - x0f, wy = y - y0f;

            float v00 = 0.f, v01 = 0.f, v10 = 0.f, v11 = 0.f;
            int x1 = x0 + 1, y1 = y0 + 1;
            bool vx0 = (x0 >= 0) & (x0 < Ww);
            bool vx1 = (x1 >= 0) & (x1 < Ww);
            bool vy0 = (y0 >= 0) & (y0 < Hh);
            bool vy1 = (y1 >= 0) & (y1 < Hh);
            size_t rowBase = (size_t)(b * SLEN + st);
            if (vy0) {
                size_t rb = rowBase + (size_t)y0 * Ww;
                if (vx0) v00 = g_value[((rb + x0) * NHEADS + h) * HDIM + lane];
                if (vx1) v01 = g_value[((rb + x1) * NHEADS + h) * HDIM + lane];
            }
            if (vy1) {
                size_t rb = rowBase + (size_t)y1 * Ww;
                if (vx0) v10 = g_value[((rb + x0) * NHEADS + h) * HDIM + lane];
                if (vx1) v11 = g_value[((rb + x1) * NHEADS + h) * HDIM + lane];
            }
            float top = v00 + (v01 - v00) * wx;
            float bot = v10 + (v11 - v10) * wx;
            acc += w * (top + (bot - top) * wy);
        }
    }
    __nv_bfloat16 hh, ll; split2(acc, hh, ll);
    int c = h * HDIM + lane;
    size_t base = (size_t)tok * 768;
    o3[base + c] = hh;
    o3[base + 256 + c] = hh;
    o3[base + 512 + c] = ll;
}

// ================= launch =================
extern "C" void kernel_launch(void* const* d_in, const int* in_sizes, int n_in,
                              void* d_out, int out_size) {
    const float* src  = (const float*)d_in[0];
    const float* pos  = (const float*)d_in[1];
    const float* refp = (const float*)d_in[2];
    const float* n1g = (const float*)d_in[5];
    const float* n1b = (const float*)d_in[6];
    const float* n2g = (const float*)d_in[7];
    const float* n2b = (const float*)d_in[8];
    const float* Wv  = (const float*)d_in[9];
    const float* bv  = (const float*)d_in[10];
    const float* Wo  = (const float*)d_in[11];
    const float* bo  = (const float*)d_in[12];
    const float* Wa  = (const float*)d_in[13];
    const float* ba  = (const float*)d_in[14];
    const float* Wout= (const float*)d_in[15];
    const float* bout= (const float*)d_in[16];
    const float* Wf1 = (const float*)d_in[17];
    const float* bf1 = (const float*)d_in[18];
    const float* Wf2 = (const float*)d_in[19];
    const float* bf2 = (const float*)d_in[20];
    float* out = (float*)d_out;

    __nv_bfloat16 *src3, *q3, *samp3, *h23, *ffn3;
    __nv_bfloat16 *wv3, *wof3, *wat3, *wo3, *wf13, *wf23;
    float *pVal, *pOff, *pAttn, *pSrc2;
    cudaGetSymbolAddress((void**)&src3, g_src3);
    cudaGetSymbolAddress((void**)&q3,   g_q3);
    cudaGetSymbolAddress((void**)&samp3,g_samp3);
    cudaGetSymbolAddress((void**)&h23,  g_h23);
    cudaGetSymbolAddress((void**)&ffn3, g_ffn3);
    cudaGetSymbolAddress((void**)&wv3,  w3_v);
    cudaGetSymbolAddress((void**)&wof3, w3_of);
    cudaGetSymbolAddress((void**)&wat3, w3_at);
    cudaGetSymbolAddress((void**)&wo3,  w3_o);
    cudaGetSymbolAddress((void**)&wf13, w3_f1);
    cudaGetSymbolAddress((void**)&wf23, w3_f2);
    cudaGetSymbolAddress((void**)&pVal, g_value);
    cudaGetSymbolAddress((void**)&pOff, g_off);
    cudaGetSymbolAddress((void**)&pAttn,g_attn);
    cudaGetSymbolAddress((void**)&pSrc2,g_src2);

    cudaFuncSetAttribute(mma_gemm<0>, cudaFuncAttributeMaxDynamicSharedMemorySize, GEMM_SMEM);
    cudaFuncSetAttribute(mma_gemm<1>, cudaFuncAttributeMaxDynamicSharedMemorySize, GEMM_SMEM);
    cudaFuncSetAttribute(mma_gemm<2>, cudaFuncAttributeMaxDynamicSharedMemorySize, GEMM_SMEM);

    dim3 t256(256);
    const int MB = NTOK / 128;   // 340

    // ---- prep: weights -> bf16x3 transposed; src/q -> bf16x3 cat ----
    wprep_kernel<<<(256*256 + 255)/256, t256>>>(Wv,  wv3,  256, 256);
    wprep_kernel<<<(256*256 + 255)/256, t256>>>(Wo,  wof3, 256, 256);
    wprep_kernel<<<(256*128 + 255)/256, t256>>>(Wa,  wat3, 256, 128);
    wprep_kernel<<<(256*256 + 255)/256, t256>>>(Wout,wo3,  256, 256);
    wprep_kernel<<<(256*1024 + 255)/256, t256>>>(Wf1, wf13, 256, 1024);
    wprep_kernel<<<(1024*256 + 255)/256, t256>>>(Wf2, wf23, 1024, 256);
    split_kernel<<<(NTOK*D_MODEL + 255)/256, t256>>>(src, src3);
    ln_kernel<<<NTOK, t256>>>(src, n1g, n1b, pos, q3);

    // ---- value / offsets / attention logits ----
    mma_gemm<0><<<dim3(2, MB), t256, GEMM_SMEM>>>(src3, wv3, bv, nullptr, pVal, nullptr, 256, 768);
    mma_gemm<0><<<dim3(2, MB), t256, GEMM_SMEM>>>(q3, wof3, bo, nullptr, pOff, nullptr, 256, 768);
    mma_gemm<0><<<dim3(1, MB), t256, GEMM_SMEM>>>(q3, wat3, ba, nullptr, pAttn, nullptr, 128, 768);
    softmax16_kernel<<<(NTOK*NHEADS + 255)/256, t256>>>(pAttn, NTOK * NHEADS);

    // ---- deformable sampling ----
    deform_kernel<<<(NTOK * NHEADS) / 8, t256>>>(refp, samp3);

    // ---- output proj + residual; LN2; FFN ----
    mma_gemm<2><<<dim3(2, MB), t256, GEMM_SMEM>>>(samp3, wo3, bout, src, pSrc2, nullptr, 256, 768);
    ln_kernel<<<NTOK, t256>>>(pSrc2, n2g, n2b, nullptr, h23);
    mma_gemm<1><<<dim3(8, MB), t256, GEMM_SMEM>>>(h23, wf13, bf1, nullptr, nullptr, ffn3, 1024, 768);
    mma_gemm<2><<<dim3(2, MB), t256, GEMM_SMEM>>>(ffn3, wf23, bf2, pSrc2, out, nullptr, 256, 3072);
}

// round 4
// speedup vs baseline: 1.9768x; 1.0123x over previous
#include <cuda_runtime.h>
#include <cuda_bf16.h>
#include <math.h>
#include <stdint.h>

#define D_MODEL 256
#define D_FFN   1024
#define NHEADS  8
#define NLEV    4
#define NPTS    4
#define HDIM    32
#define BATCH   2
#define SLEN    21760
#define NTOK    (BATCH * SLEN)   // 43520

// ================= scratch (device globals; no allocation allowed) =================
// activations in bf16x2 "[hi|lo]" layout, row length 2K
__device__ __align__(16) __nv_bfloat16 g_src2b[NTOK * 512];
__device__ __align__(16) __nv_bfloat16 g_q2[NTOK * 512];
__device__ __align__(16) __nv_bfloat16 g_samp2[NTOK * 512];
__device__ __align__(16) __nv_bfloat16 g_h22[NTOK * 512];
__device__ __align__(16) __nv_bfloat16 g_ffn2b[NTOK * 2048];

__device__ float g_value[NTOK * D_MODEL];
__device__ float g_off[NTOK * D_MODEL];
__device__ float g_attn[NTOK * NHEADS * 16];
__device__ float g_src2[NTOK * D_MODEL];

// weights transposed [N][2K] = [hi | lo]
__device__ __align__(16) __nv_bfloat16 w2_v[256 * 512];
__device__ __align__(16) __nv_bfloat16 w2_qa[384 * 512];     // rows 0-255: W_off, 256-383: W_attn
__device__ __align__(16) __nv_bfloat16 w2_o[256 * 512];
__device__ __align__(16) __nv_bfloat16 w2_f1[1024 * 512];
__device__ __align__(16) __nv_bfloat16 w2_f2[256 * 2048];

// ================= helpers =================
__device__ __forceinline__ uint32_t smem_u32(const void* p) {
    uint32_t a;
    asm("{ .reg .u64 t; cvta.to.shared.u64 t, %1; cvt.u32.u64 %0, t; }" : "=r"(a) : "l"(p));
    return a;
}
__device__ __forceinline__ void ldm_x4(uint32_t* r, uint32_t addr) {
    asm volatile("ldmatrix.sync.aligned.m8n8.x4.shared.b16 {%0,%1,%2,%3}, [%4];"
                 : "=r"(r[0]), "=r"(r[1]), "=r"(r[2]), "=r"(r[3]) : "r"(addr));
}
__device__ __forceinline__ void mma16816(float* d, const uint32_t* a, const uint32_t* b) {
    asm volatile("mma.sync.aligned.m16n8k16.row.col.f32.bf16.bf16.f32 "
                 "{%0,%1,%2,%3}, {%4,%5,%6,%7}, {%8,%9}, {%0,%1,%2,%3};"
                 : "+f"(d[0]), "+f"(d[1]), "+f"(d[2]), "+f"(d[3])
                 : "r"(a[0]), "r"(a[1]), "r"(a[2]), "r"(a[3]), "r"(b[0]), "r"(b[1]));
}
__device__ __forceinline__ void cpa16(uint32_t dst, const void* src) {
    asm volatile("cp.async.cg.shared.global [%0], [%1], 16;" :: "r"(dst), "l"(src));
}
__device__ __forceinline__ void split2(float x, __nv_bfloat16& h, __nv_bfloat16& l) {
    h = __float2bfloat16(x);
    l = __float2bfloat16(x - __bfloat162float(h));
}

// ================= HMMA GEMM with bf16x3 terms from bf16x2 storage =================
// Logical: C[M,N] = epi( Ahi·Bhi + Ahi·Blo + Alo·Bhi + bias )
// A stored [hi|lo] rowlen 2K0; B stored [hi|lo] rowlen 2K0 (N-major).
// 3*K0/64 stages; segment map A: hi,hi,lo  B: hi,lo,hi.
// EPI: 0 = bias, fp32; 1 = gelu -> bf16x2 out (rowlen 2N); 2 = bias+residual(aux), fp32;
//      3 = dual: cols<256 -> C (rowlen 256, bias), cols>=256 -> Cb (rowlen 128, bias=aux).
static const int LDS  = 72;                  // bf16 per smem row (64 + 8 pad)
static const int LDSB = LDS * 2;             // 144 B
static const int BUFB = 128 * LDSB;          // 18432 B per operand per stage
static const int GEMM_SMEM = 6 * BUFB;       // 110592: 3 stages x (A,B)

template <int EPI>
__global__ void __launch_bounds__(256, 2) mma_gemm(
    const __nv_bfloat16* __restrict__ A2, const __nv_bfloat16* __restrict__ B2,
    const float* __restrict__ bias, const float* __restrict__ aux,
    float* __restrict__ C, float* __restrict__ Cb, __nv_bfloat16* __restrict__ C3,
    int N, int K0)
{
    extern __shared__ __align__(16) char sm[];
    const uint32_t smb = smem_u32(sm);
    const int tid = threadIdx.x;
    const int wid = tid >> 5, lane = tid & 31;
    const int wm = wid >> 2, wn = wid & 3;               // 2 x 4 warps, 64x32 tiles
    const int m0 = blockIdx.y * 128, n0 = blockIdx.x * 128;
    const int third = K0 >> 6;
    const int S = 3 * third;
    const int ldg = 2 * K0;                              // gmem row length (bf16)

    float acc[4][4][4];
    #pragma unroll
    for (int i = 0; i < 4; i++)
        #pragma unroll
        for (int j = 0; j < 4; j++)
            #pragma unroll
            for (int r = 0; r < 4; r++) acc[i][j][r] = 0.f;

    auto prefetch = [&](int s) {
        int seg = (s >= 2 * third) ? 2 : ((s >= third) ? 1 : 0);
        int sk = (s - seg * third) << 6;
        int kA = ((seg == 2) ? K0 : 0) + sk;             // A: hi,hi,lo
        int kB = ((seg == 1) ? K0 : 0) + sk;             // B: hi,lo,hi
        const uint32_t ab = smb + (uint32_t)(s % 3) * (2u * BUFB);
        const uint32_t bb = ab + BUFB;
        #pragma unroll
        for (int i = 0; i < 8; i++) {
            int c = tid + (i << 8);                      // 0..2047
            int cc = c & 1023;
            int row = cc >> 3;
            int kc  = (cc & 7) << 3;                     // bf16 elems (16B chunks)
            uint32_t dst; const __nv_bfloat16* src;
            if (c < 1024) {
                dst = ab + (uint32_t)(row * LDSB + kc * 2);
                src = A2 + (size_t)(m0 + row) * ldg + kA + kc;
            } else {
                dst = bb + (uint32_t)(row * LDSB + kc * 2);
                src = B2 + (size_t)(n0 + row) * ldg + kB + kc;
            }
            cpa16(dst, src);
        }
        asm volatile("cp.async.commit_group;");
    };

    prefetch(0);
    if (S > 1) prefetch(1);

    for (int s = 0; s < S; s++) {
        if (s + 1 < S) asm volatile("cp.async.wait_group 1;");
        else           asm volatile("cp.async.wait_group 0;");
        __syncthreads();
        if (s + 2 < S) prefetch(s + 2);

        const uint32_t ab = smb + (uint32_t)(s % 3) * (2u * BUFB);
        const uint32_t bb = ab + BUFB;
        const uint32_t aoff = ab + (uint32_t)(((lane & 15) + wm * 64) * LDSB + (((lane >> 4) << 3)) * 2);
        const uint32_t boff = bb + (uint32_t)((((lane & 7) + ((lane >> 4) << 3)) + wn * 32) * LDSB
                                              + ((((lane >> 3) & 1) << 3)) * 2);
        #pragma unroll
        for (int ks = 0; ks < 4; ks++) {
            const uint32_t kb = (uint32_t)(ks * 16 * 2);
            uint32_t afr[4][4], bfr[4][2];
            #pragma unroll
            for (int mi = 0; mi < 4; mi++)
                ldm_x4(afr[mi], aoff + (uint32_t)(mi * 16 * LDSB) + kb);
            #pragma unroll
            for (int nj = 0; nj < 2; nj++) {
                uint32_t r[4];
                ldm_x4(r, boff + (uint32_t)(nj * 16 * LDSB) + kb);
                bfr[nj * 2][0] = r[0]; bfr[nj * 2][1] = r[1];
                bfr[nj * 2 + 1][0] = r[2]; bfr[nj * 2 + 1][1] = r[3];
            }
            #pragma unroll
            for (int mi = 0; mi < 4; mi++)
                #pragma unroll
                for (int ni = 0; ni < 4; ni++)
                    mma16816(acc[mi][ni], afr[mi], bfr[ni]);
        }
    }
    __syncthreads();

    // ---- epilogue: stage warp's 64x32 tile in smem (stride 36), store coalesced ----
    float* ws = (float*)sm + wid * (64 * 36);
    const int er = lane >> 2, ec = (lane & 3) * 2;
    #pragma unroll
    for (int mi = 0; mi < 4; mi++)
        #pragma unroll
        for (int ni = 0; ni < 4; ni++) {
            *(float2*)&ws[(mi * 16 + er) * 36 + ni * 8 + ec]     = make_float2(acc[mi][ni][0], acc[mi][ni][1]);
            *(float2*)&ws[(mi * 16 + er + 8) * 36 + ni * 8 + ec] = make_float2(acc[mi][ni][2], acc[mi][ni][3]);
        }
    __syncwarp();

    const int gc = n0 + wn * 32 + lane;
    float badd;
    if (EPI == 3) badd = (gc < 256) ? bias[gc] : aux[gc - 256];
    else          badd = bias[gc];

    for (int r = 0; r < 64; r++) {
        float v = ws[r * 36 + lane] + badd;
        const int gr = m0 + wm * 64 + r;
        if (EPI == 1) {
            v = 0.5f * v * (1.0f + erff(v * 0.70710678118654752f));
            __nv_bfloat16 h, l; split2(v, h, l);
            size_t base = (size_t)gr * (2 * (size_t)N);
            C3[base + gc] = h;
            C3[base + N + gc] = l;
        } else if (EPI == 3) {
            if (gc < 256) C[(size_t)gr * 256 + gc] = v;
            else          Cb[(size_t)gr * 128 + (gc - 256)] = v;
        } else {
            if (EPI == 2) v += aux[(size_t)gr * N + gc];
            C[(size_t)gr * N + gc] = v;
        }
    }
}

// ================= layernorm -> bf16x2 [hi|lo] (+ optional additive term) =================
__global__ void ln_kernel(const float* __restrict__ x,
                          const float* __restrict__ gamma,
                          const float* __restrict__ beta,
                          const float* __restrict__ add,
                          __nv_bfloat16* __restrict__ o2) {
    int t = blockIdx.x;
    int c = threadIdx.x;
    float v = x[t * D_MODEL + c];
    float a = v, a2 = v * v;
    #pragma unroll
    for (int o = 16; o; o >>= 1) {
        a  += __shfl_xor_sync(0xffffffffu, a,  o);
        a2 += __shfl_xor_sync(0xffffffffu, a2, o);
    }
    __shared__ float s1[8], s2[8];
    if ((c & 31) == 0) { s1[c >> 5] = a; s2[c >> 5] = a2; }
    __syncthreads();
    float sum = 0.f, sq = 0.f;
    #pragma unroll
    for (int i = 0; i < 8; i++) { sum += s1[i]; sq += s2[i]; }
    float mu  = sum * (1.0f / D_MODEL);
    float var = sq * (1.0f / D_MODEL) - mu * mu;
    float rr  = rsqrtf(var + 1e-5f);
    float y   = (v - mu) * rr * gamma[c] + beta[c];
    if (add) y += add[t * D_MODEL + c];
    __nv_bfloat16 h, l; split2(y, h, l);
    size_t base = (size_t)t * 512;
    o2[base + c] = h;
    o2[base + 256 + c] = l;
}

// ================= fp32 [M,256] -> bf16x2 =================
__global__ void split_kernel(const float* __restrict__ x, __nv_bfloat16* __restrict__ o2) {
    int i = blockIdx.x * blockDim.x + threadIdx.x;
    if (i >= NTOK * D_MODEL) return;
    int t = i >> 8, c = i & 255;
    __nv_bfloat16 h, l; split2(x[i], h, l);
    size_t base = (size_t)t * 512;
    o2[base + c] = h;
    o2[base + 256 + c] = l;
}

// ================= weight prep: W[K,N] -> B2[(n+rowOff)][2K] = [hi|lo] =================
__global__ void wprep_kernel(const float* __restrict__ W, __nv_bfloat16* __restrict__ B2,
                             int K, int N, int rowOff) {
    int i = blockIdx.x * blockDim.x + threadIdx.x;
    if (i >= K * N) return;
    int k = i / N, n = i - k * N;
    __nv_bfloat16 h, l; split2(W[i], h, l);
    size_t base = (size_t)(n + rowOff) * (2 * (size_t)K);
    B2[base + k] = h;
    B2[base + K + k] = l;
}

// ================= softmax over 16 =================
__global__ void softmax16_kernel(float* __restrict__ a, int n) {
    int i = blockIdx.x * blockDim.x + threadIdx.x;
    if (i >= n) return;
    float* p = a + (size_t)i * 16;
    float m = -1e30f;
    float v[16];
    #pragma unroll
    for (int j = 0; j < 16; j++) { v[j] = p[j]; m = fmaxf(m, v[j]); }
    float s = 0.f;
    #pragma unroll
    for (int j = 0; j < 16; j++) { v[j] = __expf(v[j] - m); s += v[j]; }
    float inv = 1.0f / s;
    #pragma unroll
    for (int j = 0; j < 16; j++) p[j] = v[j] * inv;
}

// ================= deformable attention sampling -> bf16x2 =================
__global__ void deform_kernel(const float* __restrict__ ref, __nv_bfloat16* __restrict__ o2) {
    const int lvH[4] = {128, 64, 32, 16};
    const int lvW[4] = {128, 64, 32, 16};
    const int lvS[4] = {0, 16384, 20480, 21504};

    int g = blockIdx.x * 8 + (threadIdx.x >> 5);
    int lane = threadIdx.x & 31;
    int b  = g / (SLEN * NHEADS);
    int rm = g - b * (SLEN * NHEADS);
    int qi = rm / NHEADS;
    int h  = rm - qi * NHEADS;
    int tok = b * SLEN + qi;

    float acc = 0.f;
    #pragma unroll
    for (int lvl = 0; lvl < NLEV; lvl++) {
        const int Hh = lvH[lvl], Ww = lvW[lvl], st = lvS[lvl];
        float rx = ref[((size_t)tok * NLEV + lvl) * 2 + 0];
        float ry = ref[((size_t)tok * NLEV + lvl) * 2 + 1];
        #pragma unroll
        for (int p = 0; p < NPTS; p++) {
            const float* op = g_off + (size_t)tok * 256 + (((h * NLEV + lvl) * NPTS + p) * 2);
            float x = rx * (float)Ww + op[0] - 0.5f;
            float y = ry * (float)Hh + op[1] - 0.5f;
            float w = g_attn[(size_t)tok * 128 + h * 16 + lvl * 4 + p];

            float x0f = floorf(x), y0f = floorf(y);
            int x0 = (int)x0f, y0 = (int)y0f;
            float wx = x - x0f, wy = y - y0f;

            float v00 = 0.f, v01 = 0.f, v10 = 0.f, v11 = 0.f;
            int x1 = x0 + 1, y1 = y0 + 1;
            bool vx0 = (x0 >= 0) & (x0 < Ww);
            bool vx1 = (x1 >= 0) & (x1 < Ww);
            bool vy0 = (y0 >= 0) & (y0 < Hh);
            bool vy1 = (y1 >= 0) & (y1 < Hh);
            size_t rowBase = (size_t)(b * SLEN + st);
            if (vy0) {
                size_t rb = rowBase + (size_t)y0 * Ww;
                if (vx0) v00 = __ldg(&g_value[((rb + x0) * NHEADS + h) * HDIM + lane]);
                if (vx1) v01 = __ldg(&g_value[((rb + x1) * NHEADS + h) * HDIM + lane]);
            }
            if (vy1) {
                size_t rb = rowBase + (size_t)y1 * Ww;
                if (vx0) v10 = __ldg(&g_value[((rb + x0) * NHEADS + h) * HDIM + lane]);
                if (vx1) v11 = __ldg(&g_value[((rb + x1) * NHEADS + h) * HDIM + lane]);
            }
            float top = v00 + (v01 - v00) * wx;
            float bot = v10 + (v11 - v10) * wx;
            acc += w * (top + (bot - top) * wy);
        }
    }
    __nv_bfloat16 hh, ll; split2(acc, hh, ll);
    int c = h * HDIM + lane;
    size_t base = (size_t)tok * 512;
    o2[base + c] = hh;
    o2[base + 256 + c] = ll;
}

// ================= launch =================
extern "C" void kernel_launch(void* const* d_in, const int* in_sizes, int n_in,
                              void* d_out, int out_size) {
    const float* src  = (const float*)d_in[0];
    const float* pos  = (const float*)d_in[1];
    const float* refp = (const float*)d_in[2];
    const float* n1g = (const float*)d_in[5];
    const float* n1b = (const float*)d_in[6];
    const float* n2g = (const float*)d_in[7];
    const float* n2b = (const float*)d_in[8];
    const float* Wv  = (const float*)d_in[9];
    const float* bv  = (const float*)d_in[10];
    const float* Wo  = (const float*)d_in[11];
    const float* bo  = (const float*)d_in[12];
    const float* Wa  = (const float*)d_in[13];
    const float* ba  = (const float*)d_in[14];
    const float* Wout= (const float*)d_in[15];
    const float* bout= (const float*)d_in[16];
    const float* Wf1 = (const float*)d_in[17];
    const float* bf1 = (const float*)d_in[18];
    const float* Wf2 = (const float*)d_in[19];
    const float* bf2 = (const float*)d_in[20];
    float* out = (float*)d_out;

    __nv_bfloat16 *src2b, *q2, *samp2, *h22, *ffn2b;
    __nv_bfloat16 *wv2, *wqa2, *wo2, *wf12, *wf22;
    float *pVal, *pOff, *pAttn, *pSrc2;
    cudaGetSymbolAddress((void**)&src2b, g_src2b);
    cudaGetSymbolAddress((void**)&q2,    g_q2);
    cudaGetSymbolAddress((void**)&samp2, g_samp2);
    cudaGetSymbolAddress((void**)&h22,   g_h22);
    cudaGetSymbolAddress((void**)&ffn2b, g_ffn2b);
    cudaGetSymbolAddress((void**)&wv2,   w2_v);
    cudaGetSymbolAddress((void**)&wqa2,  w2_qa);
    cudaGetSymbolAddress((void**)&wo2,   w2_o);
    cudaGetSymbolAddress((void**)&wf12,  w2_f1);
    cudaGetSymbolAddress((void**)&wf22,  w2_f2);
    cudaGetSymbolAddress((void**)&pVal,  g_value);
    cudaGetSymbolAddress((void**)&pOff,  g_off);
    cudaGetSymbolAddress((void**)&pAttn, g_attn);
    cudaGetSymbolAddress((void**)&pSrc2, g_src2);

    cudaFuncSetAttribute(mma_gemm<0>, cudaFuncAttributeMaxDynamicSharedMemorySize, GEMM_SMEM);
    cudaFuncSetAttribute(mma_gemm<1>, cudaFuncAttributeMaxDynamicSharedMemorySize, GEMM_SMEM);
    cudaFuncSetAttribute(mma_gemm<2>, cudaFuncAttributeMaxDynamicSharedMemorySize, GEMM_SMEM);
    cudaFuncSetAttribute(mma_gemm<3>, cudaFuncAttributeMaxDynamicSharedMemorySize, GEMM_SMEM);

    dim3 t256(256);
    const int MB = NTOK / 128;   // 340

    // launch order chosen so ncu (-s 5) profiles the value GEMM (6th launch)
    split_kernel<<<(NTOK*D_MODEL + 255)/256, t256>>>(src, src2b);                 // 0
    ln_kernel<<<NTOK, t256>>>(src, n1g, n1b, pos, q2);                            // 1
    wprep_kernel<<<(256*256 + 255)/256, t256>>>(Wv,  wv2,  256, 256, 0);          // 2
    wprep_kernel<<<(256*256 + 255)/256, t256>>>(Wo,  wqa2, 256, 256, 0);          // 3
    wprep_kernel<<<(256*128 + 255)/256, t256>>>(Wa,  wqa2, 256, 128, 256);        // 4
    mma_gemm<0><<<dim3(2, MB), t256, GEMM_SMEM>>>(src2b, wv2, bv, nullptr,        // 5 <- profiled
                                                  pVal, nullptr, nullptr, 256, 256);
    wprep_kernel<<<(256*256 + 255)/256, t256>>>(Wout, wo2,  256, 256, 0);         // 6
    wprep_kernel<<<(256*1024 + 255)/256, t256>>>(Wf1, wf12, 256, 1024, 0);        // 7
    wprep_kernel<<<(1024*256 + 255)/256, t256>>>(Wf2, wf22, 1024, 256, 0);        // 8

    // offsets + attention logits fused (N = 384)
    mma_gemm<3><<<dim3(3, MB), t256, GEMM_SMEM>>>(q2, wqa2, bo, ba,
                                                  pOff, pAttn, nullptr, 384, 256);
    softmax16_kernel<<<(NTOK*NHEADS + 255)/256, t256>>>(pAttn, NTOK * NHEADS);
    deform_kernel<<<(NTOK * NHEADS) / 8, t256>>>(refp, samp2);

    mma_gemm<2><<<dim3(2, MB), t256, GEMM_SMEM>>>(samp2, wo2, bout, src,
                                                  pSrc2, nullptr, nullptr, 256, 256);
    ln_kernel<<<NTOK, t256>>>(pSrc2, n2g, n2b, nullptr, h22);
    mma_gemm<1><<<dim3(8, MB), t256, GEMM_SMEM>>>(h22, wf12, bf1, nullptr,
                                                  nullptr, nullptr, ffn2b, 1024, 256);
    mma_gemm<2><<<dim3(2, MB), t256, GEMM_SMEM>>>(ffn2b, wf22, bf2, pSrc2,
                                                  out, nullptr, nullptr, 256, 1024);
}